// round 8
// baseline (speedup 1.0000x reference)
#include <cuda_runtime.h>
#include <cuda_bf16.h>
#include <cstdint>

#define NN 512
using bf16 = __nv_bfloat16;

// ---------------------------------------------------------------------------
// Device scratch (no allocation allowed)
// ---------------------------------------------------------------------------
#define DECLB(n) __device__ __align__(16) bf16 n[NN * NN]
DECLB(g_Xhi);   DECLB(g_Xlo);
DECLB(g_W1Thi); DECLB(g_W1Tlo);
DECLB(g_W2Thi); DECLB(g_W2Tlo);
DECLB(g_W2hi);  DECLB(g_W2lo);
DECLB(g_H1hi);  DECLB(g_H1lo);
DECLB(g_H2hi);  DECLB(g_H2lo);
DECLB(g_G1hi);  DECLB(g_G1lo);
DECLB(g_G2hi);  DECLB(g_G2lo);
__device__ __align__(16) float g_Acc[NN * NN];   // k-split reduction buffer
__device__ __align__(16) float g_PX [NN * NN];
__device__ __align__(16) float g_PH1[NN * NN];
__device__ __align__(16) float g_PH2[NN * NN];
__device__ __align__(16) float g_PG1[NN * NN];
__device__ __align__(16) float g_PG2[NN * NN];
__device__ int g_Cnt[64];    // per-tile counters for k-split GEMMs (self-resetting)
__device__ int g_CntG[36];   // per-tile counters for gram combine (self-resetting)

// ---------------------------------------------------------------------------
// PTX helpers (base PTX only — valid on virtual target sm_103)
// ---------------------------------------------------------------------------
__device__ __forceinline__ uint32_t smem_u32(const void* p) {
    return (uint32_t)__cvta_generic_to_shared(p);
}
__device__ __forceinline__ void ldm_x4(uint32_t a[4], uint32_t addr) {
    asm volatile("ldmatrix.sync.aligned.m8n8.x4.shared.b16 {%0,%1,%2,%3}, [%4];"
                 : "=r"(a[0]), "=r"(a[1]), "=r"(a[2]), "=r"(a[3]) : "r"(addr));
}
__device__ __forceinline__ void mma_bf16(float c[4], const uint32_t a[4],
                                         const uint32_t b[2]) {
    asm volatile(
        "mma.sync.aligned.m16n8k16.row.col.f32.bf16.bf16.f32 "
        "{%0,%1,%2,%3}, {%4,%5,%6,%7}, {%8,%9}, {%0,%1,%2,%3};"
        : "+f"(c[0]), "+f"(c[1]), "+f"(c[2]), "+f"(c[3])
        : "r"(a[0]), "r"(a[1]), "r"(a[2]), "r"(a[3]), "r"(b[0]), "r"(b[1]));
}
__device__ __forceinline__ void cp16(uint32_t dst, const void* src) {
    asm volatile("cp.async.cg.shared.global [%0], [%1], 16;" :: "r"(dst), "l"(src));
}
__device__ __forceinline__ void red_add(float* p, float v) {
    asm volatile("red.global.add.f32 [%0], %1;" :: "l"(p), "f"(v) : "memory");
}
#define CP_COMMIT() asm volatile("cp.async.commit_group;" ::: "memory")
#define CP_WAIT1()  asm volatile("cp.async.wait_group 1;" ::: "memory")

// ---------------------------------------------------------------------------
// SMEM ring: 3 stages, k32/stage (2 k16 sub-slices), 48B row stride.
// Stage (bytes): Ahi[2][64][24h]@0, Alo@6144, Bhi@12288, Blo@18432.
// Stage stride 24576 B. Total 3*24576 = 73728 B -> 2 CTAs/SM possible.
// ---------------------------------------------------------------------------
constexpr int SUB_B   = 3072;    // 64 rows * 48 B (one k16 sub-slice)
constexpr int A_LO_B  = 6144;
constexpr int B_HI_B  = 12288;
constexpr int B_LO_B  = 18432;
constexpr int STAGE_B = 24576;
constexpr int SMEM_MAIN = 3 * STAGE_B;

// ---------------------------------------------------------------------------
// CTA tile M=64, N=64, 256 threads (8 warps: 4m x 2n; warp tile 16x32).
// acc[4][4]: four m16n8 fragments per warp (ILP 4). Ring-3 cp.async pipeline:
// one group committed per iteration; wait_group 1 => stage st resident.
// ---------------------------------------------------------------------------
__device__ __forceinline__ void mainloop64(
    const bf16* __restrict__ Ahi, const bf16* __restrict__ Alo,
    const bf16* __restrict__ Bhi, const bf16* __restrict__ Blo,
    int rowBase, int colBase, int kBase, int nStages,
    uint32_t sb, float acc[4][4])
{
    const int t = threadIdx.x;
    const int lane = t & 31, wid = t >> 5;
    const int wm = wid & 3, wn = wid >> 2;

    // cp.async mapping: 4 x 16B per thread (A-hi, A-lo, B-hi, B-lo)
    const int arow = t >> 2, ac = t & 3;
    const uint32_t dA = (uint32_t)((ac >> 1) * SUB_B + arow * 48 + (ac & 1) * 16);
    const bf16* pAh = Ahi + (rowBase + arow) * NN + kBase + ac * 8;
    const bf16* pAl = Alo + (rowBase + arow) * NN + kBase + ac * 8;
    const bf16* pBh = Bhi + (colBase + arow) * NN + kBase + ac * 8;
    const bf16* pBl = Blo + (colBase + arow) * NN + kBase + ac * 8;

    auto issue = [&](int stg) {
        const uint32_t base = sb + (stg % 3) * STAGE_B;
        const int k0 = stg * 32;
        cp16(base + dA,          pAh + k0);
        cp16(base + A_LO_B + dA, pAl + k0);
        cp16(base + B_HI_B + dA, pBh + k0);
        cp16(base + B_LO_B + dA, pBl + k0);
        CP_COMMIT();
    };

    // ldmatrix offsets (bytes within a k16 sub-slice)
    const uint32_t aOff =
        (uint32_t)((wm * 16 + (lane & 15)) * 48 + (lane >> 4) * 16);
    uint32_t bOff[2];
#pragma unroll
    for (int fn2 = 0; fn2 < 2; ++fn2)
        bOff[fn2] = (uint32_t)((wn * 32 + fn2 * 16 + (lane & 7) +
                                ((lane >> 4) & 1) * 8) * 48 +
                               ((lane >> 3) & 1) * 16);

    issue(0); issue(1);
    for (int st = 0; st < nStages; ++st) {
        CP_WAIT1();
        __syncthreads();
        const uint32_t base = sb + (st % 3) * STAGE_B;
#pragma unroll
        for (int sub = 0; sub < 2; ++sub) {
            uint32_t ah[4], al[4];
            ldm_x4(ah, base + sub * SUB_B + aOff);
            ldm_x4(al, base + A_LO_B + sub * SUB_B + aOff);
#pragma unroll
            for (int fn2 = 0; fn2 < 2; ++fn2) {
                uint32_t bh[4], bl[4];
                ldm_x4(bh, base + B_HI_B + sub * SUB_B + bOff[fn2]);
                ldm_x4(bl, base + B_LO_B + sub * SUB_B + bOff[fn2]);
#pragma unroll
                for (int nf = 0; nf < 2; ++nf) {
                    float* a4 = acc[fn2 * 2 + nf];
                    mma_bf16(a4, ah, bh + 2 * nf);
                    mma_bf16(a4, ah, bl + 2 * nf);
                    mma_bf16(a4, al, bh + 2 * nf);
                }
            }
        }
        if (st + 2 < nStages) issue(st + 2);
        else CP_COMMIT();
    }
}

// Epilogue iteration: maps acc[4][4] to (row, col, value)
#define EPILOGUE_FOREACH(body)                                                \
    {                                                                         \
        const int lane = threadIdx.x & 31, wid = threadIdx.x >> 5;            \
        const int wm = wid & 3, wn = wid >> 2;                                \
        _Pragma("unroll") for (int fn2 = 0; fn2 < 2; ++fn2)                   \
        _Pragma("unroll") for (int nf = 0; nf < 2; ++nf)                      \
        _Pragma("unroll") for (int h = 0; h < 2; ++h)                         \
        _Pragma("unroll") for (int e = 0; e < 2; ++e) {                       \
            int r = rowBase + wm * 16 + (lane >> 2) + h * 8;                  \
            int c = colBase + wn * 32 + fn2 * 16 + nf * 8 + (lane & 3) * 2 + e; \
            float v = acc[fn2 * 2 + nf][h * 2 + e];                           \
            body                                                              \
        }                                                                     \
    }

__device__ __forceinline__ void split_store(bf16* hi, bf16* lo, int off, float v) {
    bf16 h = __float2bfloat16(v);
    hi[off] = h;
    lo[off] = __float2bfloat16(v - __bfloat162float(h));
}

// Last-CTA-per-tile gate. Returns true for exactly one CTA per tile.
__device__ __forceinline__ bool last_cta(int* cnt, int needed) {
    __threadfence();
    __shared__ int lastFlag;
    if (threadIdx.x == 0) {
        int old = atomicAdd(cnt, 1);
        lastFlag = (old == needed - 1) ? 1 : 0;
    }
    __syncthreads();
    if (!lastFlag) return false;
    __threadfence();  // acquire: make peers' global writes visible
    return true;
}

// ---------------------------------------------------------------------------
// Prep: split X/W2, transpose+split W1->W1T, W2->W2T; task 4: zero g_Acc,
// seed out[] with b3.
// ---------------------------------------------------------------------------
__global__ void k_prep(const float* __restrict__ X, const float* __restrict__ W1,
                       const float* __restrict__ W2, const float* __restrict__ b3,
                       float* __restrict__ out) {
    __shared__ float ts[32][33];
    const int task = blockIdx.y;
    const int t = threadIdx.y * 32 + threadIdx.x;
    if (task == 4) {
        float4* av = (float4*)g_Acc;
        av[blockIdx.x * 256 + t] = make_float4(0.f, 0.f, 0.f, 0.f);
        if (blockIdx.x == 0 && t < 128) {
            float b = b3[0];
            ((float4*)out)[t] = make_float4(b, b, b, b);
        }
        return;
    }
    const int tr = (blockIdx.x >> 4) * 32, tc = (blockIdx.x & 15) * 32;
    const int tx = threadIdx.x, ty = threadIdx.y;
    const float* src;
    bf16 *dhi, *dlo;
    bool trans;
    switch (task) {
        case 0:  src = X;  dhi = g_Xhi;   dlo = g_Xlo;   trans = false; break;
        case 1:  src = W1; dhi = g_W1Thi; dlo = g_W1Tlo; trans = true;  break;
        case 2:  src = W2; dhi = g_W2Thi; dlo = g_W2Tlo; trans = true;  break;
        default: src = W2; dhi = g_W2hi;  dlo = g_W2lo;  trans = false; break;
    }
    if (!trans) {
#pragma unroll
        for (int k = 0; k < 4; ++k) {
            int r = tr + ty + k * 8, c = tc + tx;
            split_store(dhi, dlo, r * NN + c, src[r * NN + c]);
        }
    } else {
#pragma unroll
        for (int k = 0; k < 4; ++k)
            ts[ty + k * 8][tx] = src[(tr + ty + k * 8) * NN + tc + tx];
        __syncthreads();
#pragma unroll
        for (int k = 0; k < 4; ++k) {
            int orow = tc + ty + k * 8, ocol = tr + tx;
            split_store(dhi, dlo, orow * NN + ocol, ts[tx][ty + k * 8]);
        }
    }
}

// ---------------------------------------------------------------------------
// K-split GEMMs: grid (8, 8, 4). Each CTA: K chunk of 128 (4 stages), red_add
// partials, then the LAST CTA per tile runs the fused epilogue and re-zeroes.
// Tile epilogue thread map: row = t>>2 (64 rows), 16 cols per thread.
// ---------------------------------------------------------------------------
__global__ void __launch_bounds__(256) k_gemm_x_w1t(const float* __restrict__ b1) {
    extern __shared__ char dsm[];
    const uint32_t sb = smem_u32(dsm);
    const int rowBase = blockIdx.y * 64, colBase = blockIdx.x * 64;
    float acc[4][4] = {};
    mainloop64(g_Xhi, g_Xlo, g_W1Thi, g_W1Tlo, rowBase, colBase,
               blockIdx.z * 128, 4, sb, acc);
    EPILOGUE_FOREACH({ red_add(g_Acc + r * NN + c, v); })
    int* cnt = &g_Cnt[blockIdx.y * 8 + blockIdx.x];
    if (!last_cta(cnt, 4)) return;
    const int t = threadIdx.x;
    const int r = rowBase + (t >> 2);
    const int c0 = colBase + (t & 3) * 16;
    float4* accv = (float4*)(g_Acc + r * NN + c0);
    const float4 z4 = make_float4(0.f, 0.f, 0.f, 0.f);
#pragma unroll
    for (int q = 0; q < 4; ++q) {
        float4 a = accv[q];
        float zv[4] = {a.x, a.y, a.z, a.w};
#pragma unroll
        for (int e = 0; e < 4; ++e) {
            int c = c0 + q * 4 + e;
            float hv = fmaxf(zv[e] + b1[c], 0.f);
            split_store(g_H1hi, g_H1lo, r * NN + c, hv);
        }
        accv[q] = z4;
    }
    if (t == 0) *cnt = 0;
}

__global__ void __launch_bounds__(256) k_gemm_h1_w2t(const float* __restrict__ b2,
                                                     const float* __restrict__ w3,
                                                     float* __restrict__ out) {
    extern __shared__ char dsm[];
    const uint32_t sb = smem_u32(dsm);
    const int rowBase = blockIdx.y * 64, colBase = blockIdx.x * 64;
    float acc[4][4] = {};
    mainloop64(g_H1hi, g_H1lo, g_W2Thi, g_W2Tlo, rowBase, colBase,
               blockIdx.z * 128, 4, sb, acc);
    EPILOGUE_FOREACH({ red_add(g_Acc + r * NN + c, v); })
    int* cnt = &g_Cnt[blockIdx.y * 8 + blockIdx.x];
    if (!last_cta(cnt, 4)) return;
    const int t = threadIdx.x;
    const int r = rowBase + (t >> 2);
    const int c0 = colBase + (t & 3) * 16;
    float4* accv = (float4*)(g_Acc + r * NN + c0);
    const float4 z4 = make_float4(0.f, 0.f, 0.f, 0.f);
    float s = 0.f;
#pragma unroll
    for (int q = 0; q < 4; ++q) {
        float4 a = accv[q];
        float zv[4] = {a.x, a.y, a.z, a.w};
#pragma unroll
        for (int e = 0; e < 4; ++e) {
            int c = c0 + q * 4 + e;
            float z = zv[e] + b2[c];
            float hv = fmaxf(z, 0.f);
            int off = r * NN + c;
            split_store(g_H2hi, g_H2lo, off, hv);
            float wj = w3[c];
            float g = (z > 0.f) ? wj : 0.f;
            split_store(g_G2hi, g_G2lo, off, g);
            s += hv * wj;
        }
        accv[q] = z4;
    }
    // reduce the 4 threads covering this row (lanes differ in bits 0-1)
    s += __shfl_xor_sync(0xffffffffu, s, 1);
    s += __shfl_xor_sync(0xffffffffu, s, 2);
    if ((t & 3) == 0) red_add(out + r, s);
    if (t == 0) *cnt = 0;
}

__global__ void __launch_bounds__(256) k_gemm_g2_w2() {
    extern __shared__ char dsm[];
    const uint32_t sb = smem_u32(dsm);
    const int rowBase = blockIdx.y * 64, colBase = blockIdx.x * 64;
    float acc[4][4] = {};
    mainloop64(g_G2hi, g_G2lo, g_W2hi, g_W2lo, rowBase, colBase,
               blockIdx.z * 128, 4, sb, acc);
    EPILOGUE_FOREACH({ red_add(g_Acc + r * NN + c, v); })
    int* cnt = &g_Cnt[blockIdx.y * 8 + blockIdx.x];
    if (!last_cta(cnt, 4)) return;
    const int t = threadIdx.x;
    const int r = rowBase + (t >> 2);
    const int c0 = colBase + (t & 3) * 16;
    float4* accv = (float4*)(g_Acc + r * NN + c0);
    const float4 z4 = make_float4(0.f, 0.f, 0.f, 0.f);
#pragma unroll
    for (int q = 0; q < 4; ++q) {
        float4 a = accv[q];
        float vv[4] = {a.x, a.y, a.z, a.w};
#pragma unroll
        for (int e = 0; e < 4; ++e) {
            int c = c0 + q * 4 + e;
            int off = r * NN + c;
            float m = (__bfloat162float(g_H1hi[off]) > 0.f) ? vv[e] : 0.f;
            split_store(g_G1hi, g_G1lo, off, m);
        }
        accv[q] = z4;
    }
    if (t == 0) *cnt = 0;
}

// ---------------------------------------------------------------------------
// Gram: lower-triangle 64x64 blocks (36) x 5 matrices; last CTA per tile
// combines all 5 partials + mirrors (fused k_combine).
// ---------------------------------------------------------------------------
__device__ __forceinline__ void tri36(int L, int& rb, int& cb) {
    int r = 0;
    while (L >= r + 1) { L -= r + 1; ++r; }
    rb = r; cb = L;
}

__global__ void __launch_bounds__(256) k_gram(float* __restrict__ gram) {
    extern __shared__ char dsm[];
    const uint32_t sb = smem_u32(dsm);
    int rb, cb;
    tri36(blockIdx.x, rb, cb);
    const bf16 *Ahi, *Alo;
    float* P;
    switch (blockIdx.y) {
        case 0:  Ahi = g_Xhi;  Alo = g_Xlo;  P = g_PX;  break;
        case 1:  Ahi = g_H1hi; Alo = g_H1lo; P = g_PH1; break;
        case 2:  Ahi = g_H2hi; Alo = g_H2lo; P = g_PH2; break;
        case 3:  Ahi = g_G1hi; Alo = g_G1lo; P = g_PG1; break;
        default: Ahi = g_G2hi; Alo = g_G2lo; P = g_PG2; break;
    }
    const int rowBase = rb * 64, colBase = cb * 64;
    float acc[4][4] = {};
    mainloop64(Ahi, Alo, Ahi, Alo, rowBase, colBase, 0, 16, sb, acc);
    EPILOGUE_FOREACH({ P[r * NN + c] = v; })
    int* cnt = &g_CntG[blockIdx.x];
    if (!last_cta(cnt, 5)) return;
    for (int idx = threadIdx.x; idx < 64 * 64; idx += 256) {
        int r = idx >> 6, c = idx & 63;
        int i = rowBase + r, j = colBase + c;
        if (j > i) continue;
        int off = i * NN + j;
        float g = 1.f + g_PH2[off] + g_PG2[off] * (1.f + g_PH1[off]) +
                  g_PG1[off] * (1.f + g_PX[off]);
        gram[off] = g;
        gram[j * NN + i] = g;
    }
    if (threadIdx.x == 0) *cnt = 0;
}

// ---------------------------------------------------------------------------
// Launch (5 kernels)
// ---------------------------------------------------------------------------
extern "C" void kernel_launch(void* const* d_in, const int* in_sizes, int n_in,
                              void* d_out, int out_size) {
    const float* x  = (const float*)d_in[0];
    const float* W1 = (const float*)d_in[1];
    const float* b1 = (const float*)d_in[2];
    const float* W2 = (const float*)d_in[3];
    const float* b2 = (const float*)d_in[4];
    const float* w3 = (const float*)d_in[5];
    const float* b3 = (const float*)d_in[6];

    float* out  = (float*)d_out;       // [512]
    float* gram = (float*)d_out + NN;  // [512 x 512]

    cudaFuncSetAttribute(k_gemm_x_w1t,  cudaFuncAttributeMaxDynamicSharedMemorySize, SMEM_MAIN);
    cudaFuncSetAttribute(k_gemm_h1_w2t, cudaFuncAttributeMaxDynamicSharedMemorySize, SMEM_MAIN);
    cudaFuncSetAttribute(k_gemm_g2_w2,  cudaFuncAttributeMaxDynamicSharedMemorySize, SMEM_MAIN);
    cudaFuncSetAttribute(k_gram,        cudaFuncAttributeMaxDynamicSharedMemorySize, SMEM_MAIN);

    dim3 ggrid(8, 8, 4);  // 256 CTAs, K split in 4
    k_prep<<<dim3(256, 5), dim3(32, 8)>>>(x, W1, W2, b3, out);
    k_gemm_x_w1t<<<ggrid, 256, SMEM_MAIN>>>(b1);
    k_gemm_h1_w2t<<<ggrid, 256, SMEM_MAIN>>>(b2, w3, out);
    k_gemm_g2_w2<<<ggrid, 256, SMEM_MAIN>>>();
    k_gram<<<dim3(36, 5), 256, SMEM_MAIN>>>(gram);
}

// round 10
// speedup vs baseline: 1.1323x; 1.1323x over previous
#include <cuda_runtime.h>
#include <cuda_bf16.h>
#include <cstdint>

#define NN 512
using bf16 = __nv_bfloat16;

// ---------------------------------------------------------------------------
// Device scratch (no allocation allowed)
// ---------------------------------------------------------------------------
#define DECLB(n) __device__ __align__(16) bf16 n[NN * NN]
DECLB(g_Xhi);   DECLB(g_Xlo);
DECLB(g_W1Thi); DECLB(g_W1Tlo);
DECLB(g_W2Thi); DECLB(g_W2Tlo);
DECLB(g_W2hi);  DECLB(g_W2lo);
DECLB(g_H1hi);  DECLB(g_H1lo);
DECLB(g_H2hi);  DECLB(g_H2lo);
DECLB(g_G1hi);  DECLB(g_G1lo);
DECLB(g_G2hi);  DECLB(g_G2lo);
__device__ __align__(16) float g_PX [NN * NN];
__device__ __align__(16) float g_PH1[NN * NN];
__device__ __align__(16) float g_PH2[NN * NN];
__device__ __align__(16) float g_PG1[NN * NN];
__device__ __align__(16) float g_PG2[NN * NN];
__device__ int g_CntG[36];   // per-tile counters for gram combine (self-resetting)

// ---------------------------------------------------------------------------
// PTX helpers (base PTX only — valid on virtual target sm_103)
// ---------------------------------------------------------------------------
__device__ __forceinline__ uint32_t smem_u32(const void* p) {
    return (uint32_t)__cvta_generic_to_shared(p);
}
__device__ __forceinline__ void ldm_x4(uint32_t a[4], uint32_t addr) {
    asm volatile("ldmatrix.sync.aligned.m8n8.x4.shared.b16 {%0,%1,%2,%3}, [%4];"
                 : "=r"(a[0]), "=r"(a[1]), "=r"(a[2]), "=r"(a[3]) : "r"(addr));
}
__device__ __forceinline__ void mma_bf16(float c[4], const uint32_t a[4],
                                         const uint32_t b[2]) {
    asm volatile(
        "mma.sync.aligned.m16n8k16.row.col.f32.bf16.bf16.f32 "
        "{%0,%1,%2,%3}, {%4,%5,%6,%7}, {%8,%9}, {%0,%1,%2,%3};"
        : "+f"(c[0]), "+f"(c[1]), "+f"(c[2]), "+f"(c[3])
        : "r"(a[0]), "r"(a[1]), "r"(a[2]), "r"(a[3]), "r"(b[0]), "r"(b[1]));
}
__device__ __forceinline__ void cp16(uint32_t dst, const void* src) {
    asm volatile("cp.async.cg.shared.global [%0], [%1], 16;" :: "r"(dst), "l"(src));
}
__device__ __forceinline__ void red_add(float* p, float v) {
    asm volatile("red.global.add.f32 [%0], %1;" :: "l"(p), "f"(v) : "memory");
}
#define CP_COMMIT() asm volatile("cp.async.commit_group;" ::: "memory")
#define CP_WAIT0()  asm volatile("cp.async.wait_group 0;" ::: "memory")
#define CP_WAIT1()  asm volatile("cp.async.wait_group 1;" ::: "memory")
#define CP_WAIT2()  asm volatile("cp.async.wait_group 2;" ::: "memory")

__device__ __forceinline__ void split_store(bf16* hi, bf16* lo, int off, float v) {
    bf16 h = __float2bfloat16(v);
    hi[off] = h;
    lo[off] = __float2bfloat16(v - __bfloat162float(h));
}

// ===========================================================================
// FWD mainloop: CTA tile M=64, N=32, 256 threads = 8 warps (4m x 2k).
// In-CTA split-K: warp group wk handles K-half (stages of parity wk).
// Ring of 6 k32-stages; 2 stages consumed per iteration (one per group).
// Stage layout (bytes): Ahi[2sub][64][24h]@0, Alo@6144, Bhi[2][32][24h]@12288,
// Blo@15360. Stage stride 18432. Total 6*18432 = 110592 (dynamic).
// ===========================================================================
constexpr int F_SUBA  = 3072;    // 64 rows * 48 B
constexpr int F_SUBB  = 1536;    // 32 rows * 48 B
constexpr int F_ALO   = 6144;
constexpr int F_BHI   = 12288;
constexpr int F_BLO   = 15360;
constexpr int F_STAGE = 18432;
constexpr int F_SMEM  = 6 * F_STAGE;   // 110592

__device__ __forceinline__ void mainloop32(
    const bf16* __restrict__ Ahi, const bf16* __restrict__ Alo,
    const bf16* __restrict__ Bhi, const bf16* __restrict__ Blo,
    int rowBase, int colBase, uint32_t sb, float acc[4][4])
{
    const int t = threadIdx.x;
    const int lane = t & 31, wid = t >> 5;
    const int wm = wid & 3, wk = wid >> 2;

    // cp.async mapping: A = 256 chunks (1 hi + 1 lo per thread), B = 128x2 (1/thread)
    const int arow = t >> 2, ac = t & 3;
    const uint32_t dA = (uint32_t)((ac >> 1) * F_SUBA + arow * 48 + (ac & 1) * 16);
    const int u = t & 127;
    const int brow = u >> 2, bc = u & 3;
    const uint32_t dB = (uint32_t)((t < 128 ? F_BHI : F_BLO) +
                                   (bc >> 1) * F_SUBB + brow * 48 + (bc & 1) * 16);
    const bf16* pAh = Ahi + (rowBase + arow) * NN + ac * 8;
    const bf16* pAl = Alo + (rowBase + arow) * NN + ac * 8;
    const bf16* pB  = (t < 128 ? Bhi : Blo) + (colBase + brow) * NN + bc * 8;

    auto issue = [&](int stg) {
        const uint32_t base = sb + (stg % 6) * F_STAGE;
        const int k0 = stg * 32;
        cp16(base + dA,         pAh + k0);
        cp16(base + F_ALO + dA, pAl + k0);
        cp16(base + dB,         pB + k0);
        CP_COMMIT();
    };

    const uint32_t aOff =
        (uint32_t)((wm * 16 + (lane & 15)) * 48 + (lane >> 4) * 16);
    uint32_t bOff[2];
#pragma unroll
    for (int g = 0; g < 2; ++g)
        bOff[g] = (uint32_t)((g * 16 + (lane & 7) + ((lane >> 4) & 1) * 8) * 48 +
                             ((lane >> 3) & 1) * 16);

    issue(0); issue(1); issue(2); issue(3);
    for (int it = 0; it < 8; ++it) {
        if (it < 7) { CP_WAIT2(); } else { CP_WAIT0(); }
        __syncthreads();
        const int s = 2 * it + wk;            // this group's stage
        const uint32_t base = sb + (s % 6) * F_STAGE;
#pragma unroll
        for (int sub = 0; sub < 2; ++sub) {
            uint32_t ah[4], al[4];
            ldm_x4(ah, base + sub * F_SUBA + aOff);
            ldm_x4(al, base + F_ALO + sub * F_SUBA + aOff);
#pragma unroll
            for (int g = 0; g < 2; ++g) {
                uint32_t bh[4], bl[4];
                ldm_x4(bh, base + F_BHI + sub * F_SUBB + bOff[g]);
                ldm_x4(bl, base + F_BLO + sub * F_SUBB + bOff[g]);
#pragma unroll
                for (int nf = 0; nf < 2; ++nf) {
                    float* a4 = acc[g * 2 + nf];
                    mma_bf16(a4, ah, bh + 2 * nf);
                    mma_bf16(a4, ah, bl + 2 * nf);
                    mma_bf16(a4, al, bh + 2 * nf);
                }
            }
        }
        if (it < 6) { issue(2 * it + 4); issue(2 * it + 5); }
    }
}

// Cross-group K-reduction + fused epilogue. Group 1 stores to smem, group 0
// adds its half and applies `epi`.
template <typename EPI>
__device__ __forceinline__ void reduce_and_epilogue(char* dsm, float acc[4][4],
                                                    int rowBase, int colBase,
                                                    EPI epi) {
    const int t = threadIdx.x;
    const int lane = t & 31, wid = t >> 5;
    const int wm = wid & 3, wk = wid >> 2;
    __syncthreads();
    float* red = (float*)dsm;    // 64 x 32 floats = 8 KB (reuses ring)
    if (wk == 1) {
#pragma unroll
        for (int fn = 0; fn < 4; ++fn)
#pragma unroll
            for (int h = 0; h < 2; ++h)
#pragma unroll
                for (int e = 0; e < 2; ++e) {
                    int r = wm * 16 + (lane >> 2) + h * 8;
                    int c = fn * 8 + (lane & 3) * 2 + e;
                    red[r * 32 + c] = acc[fn][h * 2 + e];
                }
    }
    __syncthreads();
    if (wk == 0) {
#pragma unroll
        for (int fn = 0; fn < 4; ++fn)
#pragma unroll
            for (int h = 0; h < 2; ++h)
#pragma unroll
                for (int e = 0; e < 2; ++e) {
                    int rl = wm * 16 + (lane >> 2) + h * 8;
                    int cl = fn * 8 + (lane & 3) * 2 + e;
                    float v = acc[fn][h * 2 + e] + red[rl * 32 + cl];
                    epi(rowBase + rl, colBase + cl, v, h);
                }
    }
}

// ---------------------------------------------------------------------------
// Prep: split X/W2, transpose+split W1->W1T, W2->W2T; task 4: seed out with b3
// ---------------------------------------------------------------------------
__global__ void k_prep(const float* __restrict__ X, const float* __restrict__ W1,
                       const float* __restrict__ W2, const float* __restrict__ b3,
                       float* __restrict__ out) {
    __shared__ float ts[32][33];
    const int task = blockIdx.y;
    const int t = threadIdx.y * 32 + threadIdx.x;
    if (task == 4) {
        if (blockIdx.x == 0 && t < 128) {
            float b = b3[0];
            ((float4*)out)[t] = make_float4(b, b, b, b);
        }
        return;
    }
    const int tr = (blockIdx.x >> 4) * 32, tc = (blockIdx.x & 15) * 32;
    const int tx = threadIdx.x, ty = threadIdx.y;
    const float* src;
    bf16 *dhi, *dlo;
    bool trans;
    switch (task) {
        case 0:  src = X;  dhi = g_Xhi;   dlo = g_Xlo;   trans = false; break;
        case 1:  src = W1; dhi = g_W1Thi; dlo = g_W1Tlo; trans = true;  break;
        case 2:  src = W2; dhi = g_W2Thi; dlo = g_W2Tlo; trans = true;  break;
        default: src = W2; dhi = g_W2hi;  dlo = g_W2lo;  trans = false; break;
    }
    if (!trans) {
#pragma unroll
        for (int k = 0; k < 4; ++k) {
            int r = tr + ty + k * 8, c = tc + tx;
            split_store(dhi, dlo, r * NN + c, src[r * NN + c]);
        }
    } else {
#pragma unroll
        for (int k = 0; k < 4; ++k)
            ts[ty + k * 8][tx] = src[(tr + ty + k * 8) * NN + tc + tx];
        __syncthreads();
#pragma unroll
        for (int k = 0; k < 4; ++k) {
            int orow = tc + ty + k * 8, ocol = tr + tx;
            split_store(dhi, dlo, orow * NN + ocol, ts[tx][ty + k * 8]);
        }
    }
}

// ---------------------------------------------------------------------------
// FWD GEMM kernels: grid (16, 8) = 128 CTAs, fused epilogues, no atomics
// (except tiny per-row red.add for `out` in fwd2).
// ---------------------------------------------------------------------------
struct EpiH1 {
    const float* b1;
    __device__ void operator()(int r, int c, float v, int) const {
        float hv = fmaxf(v + b1[c], 0.f);
        split_store(g_H1hi, g_H1lo, r * NN + c, hv);
    }
};

__global__ void __launch_bounds__(256) k_fwd1(const float* __restrict__ b1) {
    extern __shared__ char dsm[];
    const uint32_t sb = smem_u32(dsm);
    const int rowBase = blockIdx.y * 64, colBase = blockIdx.x * 32;
    float acc[4][4] = {};
    mainloop32(g_Xhi, g_Xlo, g_W1Thi, g_W1Tlo, rowBase, colBase, sb, acc);
    EpiH1 epi{b1};
    reduce_and_epilogue(dsm, acc, rowBase, colBase, epi);
}

struct EpiH2 {
    const float* b2;
    const float* w3;
    float* s;
    __device__ void operator()(int r, int c, float v, int h) const {
        float z = v + b2[c];
        float hv = fmaxf(z, 0.f);
        int off = r * NN + c;
        split_store(g_H2hi, g_H2lo, off, hv);
        float wj = w3[c];
        float g = (z > 0.f) ? wj : 0.f;
        split_store(g_G2hi, g_G2lo, off, g);
        s[h] += hv * wj;
    }
};

__global__ void __launch_bounds__(256) k_fwd2(const float* __restrict__ b2,
                                              const float* __restrict__ w3,
                                              float* __restrict__ out) {
    extern __shared__ char dsm[];
    const uint32_t sb = smem_u32(dsm);
    const int rowBase = blockIdx.y * 64, colBase = blockIdx.x * 32;
    float acc[4][4] = {};
    mainloop32(g_H1hi, g_H1lo, g_W2Thi, g_W2Tlo, rowBase, colBase, sb, acc);
    float s[2] = {0.f, 0.f};
    EpiH2 epi{b2, w3, s};
    reduce_and_epilogue(dsm, acc, rowBase, colBase, epi);
    // row-partial dot: reduce lanes sharing the same row (lane bits 0-1)
    const int t = threadIdx.x, lane = t & 31, wid = t >> 5;
    if ((wid >> 2) == 0) {
#pragma unroll
        for (int h = 0; h < 2; ++h) {
            float v = s[h];
            v += __shfl_xor_sync(0xffffffffu, v, 1);
            v += __shfl_xor_sync(0xffffffffu, v, 2);
            if ((lane & 3) == 0)
                red_add(out + rowBase + (wid & 3) * 16 + (lane >> 2) + h * 8, v);
        }
    }
}

struct EpiG1 {
    __device__ void operator()(int r, int c, float v, int) const {
        int off = r * NN + c;
        float m = (__bfloat162float(g_H1hi[off]) > 0.f) ? v : 0.f;
        split_store(g_G1hi, g_G1lo, off, m);
    }
};

__global__ void __launch_bounds__(256) k_g1() {
    extern __shared__ char dsm[];
    const uint32_t sb = smem_u32(dsm);
    const int rowBase = blockIdx.y * 64, colBase = blockIdx.x * 32;
    float acc[4][4] = {};
    mainloop32(g_G2hi, g_G2lo, g_W2hi, g_W2lo, rowBase, colBase, sb, acc);
    EpiG1 epi{};
    reduce_and_epilogue(dsm, acc, rowBase, colBase, epi);
}

// ===========================================================================
// GRAM: CTA tile 64x64, 8 warps (4m x 2n), ILP-4, ring-3, full K (as R7).
// ===========================================================================
constexpr int G_SUB   = 3072;
constexpr int G_ALO   = 6144;
constexpr int G_BHI   = 12288;
constexpr int G_BLO   = 18432;
constexpr int G_STAGE = 24576;
constexpr int G_SMEM  = 3 * G_STAGE;   // 73728

__device__ __forceinline__ void mainloop64(
    const bf16* __restrict__ Ahi, const bf16* __restrict__ Alo,
    int rowBase, int colBase, uint32_t sb, float acc[4][4])
{
    const int t = threadIdx.x;
    const int lane = t & 31, wid = t >> 5;
    const int wm = wid & 3, wn = wid >> 2;

    const int arow = t >> 2, ac = t & 3;
    const uint32_t dA = (uint32_t)((ac >> 1) * G_SUB + arow * 48 + (ac & 1) * 16);
    const bf16* pAh = Ahi + (rowBase + arow) * NN + ac * 8;
    const bf16* pAl = Alo + (rowBase + arow) * NN + ac * 8;
    const bf16* pBh = Ahi + (colBase + arow) * NN + ac * 8;
    const bf16* pBl = Alo + (colBase + arow) * NN + ac * 8;

    auto issue = [&](int stg) {
        const uint32_t base = sb + (stg % 3) * G_STAGE;
        const int k0 = stg * 32;
        cp16(base + dA,         pAh + k0);
        cp16(base + G_ALO + dA, pAl + k0);
        cp16(base + G_BHI + dA, pBh + k0);
        cp16(base + G_BLO + dA, pBl + k0);
        CP_COMMIT();
    };

    const uint32_t aOff =
        (uint32_t)((wm * 16 + (lane & 15)) * 48 + (lane >> 4) * 16);
    uint32_t bOff[2];
#pragma unroll
    for (int fn2 = 0; fn2 < 2; ++fn2)
        bOff[fn2] = (uint32_t)((wn * 32 + fn2 * 16 + (lane & 7) +
                                ((lane >> 4) & 1) * 8) * 48 +
                               ((lane >> 3) & 1) * 16);

    issue(0); issue(1);
    for (int st = 0; st < 16; ++st) {
        CP_WAIT1();
        __syncthreads();
        const uint32_t base = sb + (st % 3) * G_STAGE;
#pragma unroll
        for (int sub = 0; sub < 2; ++sub) {
            uint32_t ah[4], al[4];
            ldm_x4(ah, base + sub * G_SUB + aOff);
            ldm_x4(al, base + G_ALO + sub * G_SUB + aOff);
#pragma unroll
            for (int fn2 = 0; fn2 < 2; ++fn2) {
                uint32_t bh[4], bl[4];
                ldm_x4(bh, base + G_BHI + sub * G_SUB + bOff[fn2]);
                ldm_x4(bl, base + G_BLO + sub * G_SUB + bOff[fn2]);
#pragma unroll
                for (int nf = 0; nf < 2; ++nf) {
                    float* a4 = acc[fn2 * 2 + nf];
                    mma_bf16(a4, ah, bh + 2 * nf);
                    mma_bf16(a4, ah, bl + 2 * nf);
                    mma_bf16(a4, al, bh + 2 * nf);
                }
            }
        }
        if (st + 2 < 16) issue(st + 2);
        else CP_COMMIT();
    }
}

__device__ __forceinline__ void tri36(int L, int& rb, int& cb) {
    int r = 0;
    while (L >= r + 1) { L -= r + 1; ++r; }
    rb = r; cb = L;
}

__global__ void __launch_bounds__(256) k_gram(float* __restrict__ gram) {
    extern __shared__ char dsm[];
    const uint32_t sb = smem_u32(dsm);
    int rb, cb;
    tri36(blockIdx.x, rb, cb);
    const bf16 *Ahi, *Alo;
    float* P;
    switch (blockIdx.y) {
        case 0:  Ahi = g_Xhi;  Alo = g_Xlo;  P = g_PX;  break;
        case 1:  Ahi = g_H1hi; Alo = g_H1lo; P = g_PH1; break;
        case 2:  Ahi = g_H2hi; Alo = g_H2lo; P = g_PH2; break;
        case 3:  Ahi = g_G1hi; Alo = g_G1lo; P = g_PG1; break;
        default: Ahi = g_G2hi; Alo = g_G2lo; P = g_PG2; break;
    }
    const int rowBase = rb * 64, colBase = cb * 64;
    float acc[4][4] = {};
    mainloop64(Ahi, Alo, rowBase, colBase, sb, acc);
    {
        const int lane = threadIdx.x & 31, wid = threadIdx.x >> 5;
        const int wm = wid & 3, wn = wid >> 2;
#pragma unroll
        for (int fn2 = 0; fn2 < 2; ++fn2)
#pragma unroll
            for (int nf = 0; nf < 2; ++nf)
#pragma unroll
                for (int h = 0; h < 2; ++h)
#pragma unroll
                    for (int e = 0; e < 2; ++e) {
                        int r = rowBase + wm * 16 + (lane >> 2) + h * 8;
                        int c = colBase + wn * 32 + fn2 * 16 + nf * 8 +
                                (lane & 3) * 2 + e;
                        P[r * NN + c] = acc[fn2 * 2 + nf][h * 2 + e];
                    }
    }
    // last CTA per tile combines + mirrors
    __threadfence();
    __shared__ int lastFlag;
    int* cnt = &g_CntG[blockIdx.x];
    if (threadIdx.x == 0) lastFlag = (atomicAdd(cnt, 1) == 4) ? 1 : 0;
    __syncthreads();
    if (!lastFlag) return;
    __threadfence();
    for (int idx = threadIdx.x; idx < 64 * 64; idx += 256) {
        int r = idx >> 6, c = idx & 63;
        int i = rowBase + r, j = colBase + c;
        if (j > i) continue;
        int off = i * NN + j;
        float g = 1.f + g_PH2[off] + g_PG2[off] * (1.f + g_PH1[off]) +
                  g_PG1[off] * (1.f + g_PX[off]);
        gram[off] = g;
        gram[j * NN + i] = g;
    }
    if (threadIdx.x == 0) *cnt = 0;
}

// ---------------------------------------------------------------------------
// Launch (5 kernels)
// ---------------------------------------------------------------------------
extern "C" void kernel_launch(void* const* d_in, const int* in_sizes, int n_in,
                              void* d_out, int out_size) {
    const float* x  = (const float*)d_in[0];
    const float* W1 = (const float*)d_in[1];
    const float* b1 = (const float*)d_in[2];
    const float* W2 = (const float*)d_in[3];
    const float* b2 = (const float*)d_in[4];
    const float* w3 = (const float*)d_in[5];
    const float* b3 = (const float*)d_in[6];

    float* out  = (float*)d_out;       // [512]
    float* gram = (float*)d_out + NN;  // [512 x 512]

    cudaFuncSetAttribute(k_fwd1, cudaFuncAttributeMaxDynamicSharedMemorySize, F_SMEM);
    cudaFuncSetAttribute(k_fwd2, cudaFuncAttributeMaxDynamicSharedMemorySize, F_SMEM);
    cudaFuncSetAttribute(k_g1,   cudaFuncAttributeMaxDynamicSharedMemorySize, F_SMEM);
    cudaFuncSetAttribute(k_gram, cudaFuncAttributeMaxDynamicSharedMemorySize, G_SMEM);

    dim3 fgrid(16, 8);  // 128 CTAs
    k_prep<<<dim3(256, 5), dim3(32, 8)>>>(x, W1, W2, b3, out);
    k_fwd1<<<fgrid, 256, F_SMEM>>>(b1);
    k_fwd2<<<fgrid, 256, F_SMEM>>>(b2, w3, out);
    k_g1<<<fgrid, 256, F_SMEM>>>();
    k_gram<<<dim3(36, 5), 256, G_SMEM>>>(gram);
}